// round 5
// baseline (speedup 1.0000x reference)
#include <cuda_runtime.h>
#include <cuda_fp16.h>

// Problem constants (fixed by the dataset)
#define NMAX 50048
#define EMAX 1600000
#define WDIM 64
#define HDIM 128

// Scratch (allocation-free rule: __device__ globals)
__device__ __half gA[NMAX * HDIM];     // x @ w1[0:64,:]  + b1
__device__ __half gB[NMAX * HDIM];     // x @ w1[64:128,:]
__device__ float  gDenom[NMAX];
__device__ int    gCnt[NMAX];          // per-dst edge count
__device__ int    gOff[NMAX + 1];      // exclusive prefix (bin starts)
__device__ int    gCursor[NMAX];       // scatter cursors
__device__ int4   gSorted[EMAX];       // {src, dst, orig_e, pad} sorted by dst
__device__ float  gEsort[EMAX];        // exp(logit) in sorted order

// ---------------------------------------------------------------------------
// Kernel 0: zero denom and histogram counters
// ---------------------------------------------------------------------------
__global__ void init_kernel(int N) {
    int i = blockIdx.x * blockDim.x + threadIdx.x;
    if (i < N) {
        gDenom[i] = 0.0f;
        gCnt[i]   = 0;
    }
}

// ---------------------------------------------------------------------------
// Kernel 1: per-node precompute  A[n][j] = sum_k x[n][k]*w1[k][j] + b1[j]
//                                B[n][j] = sum_k x[n][k]*w1[64+k][j]
// ---------------------------------------------------------------------------
#define TR 16
__global__ void precompute_ab(const float* __restrict__ x,
                              const float* __restrict__ w1,
                              const float* __restrict__ b1, int N) {
    __shared__ float xs[TR][WDIM];
    const int row0 = blockIdx.x * TR;
    const int tid  = threadIdx.x;

    for (int i = tid; i < TR * WDIM; i += 256) {
        int r = i >> 6, k = i & 63;
        int gr = row0 + r;
        xs[r][k] = (gr < N) ? x[gr * WDIM + k] : 0.0f;
    }
    __syncthreads();

    const int col  = tid & 127;
    const int half = tid >> 7;   // 0 -> A, 1 -> B
    const float* wbase = w1 + half * WDIM * HDIM + col;

    float acc[TR];
#pragma unroll
    for (int r = 0; r < TR; r++) acc[r] = 0.0f;

#pragma unroll 8
    for (int k = 0; k < WDIM; k++) {
        float w = __ldg(wbase + k * HDIM);
#pragma unroll
        for (int r = 0; r < TR; r++) acc[r] += xs[r][k] * w;
    }

    const float bias = (half == 0) ? __ldg(&b1[col]) : 0.0f;
    __half* out = (half == 0) ? gA : gB;
#pragma unroll
    for (int r = 0; r < TR; r++) {
        int gr = row0 + r;
        if (gr < N) out[gr * HDIM + col] = __float2half_rn(acc[r] + bias);
    }
}

// ---------------------------------------------------------------------------
// Kernel 2: histogram of dst
// ---------------------------------------------------------------------------
__global__ void hist_kernel(const int* __restrict__ dst, int E) {
    int e = blockIdx.x * blockDim.x + threadIdx.x;
    if (e < E) atomicAdd(&gCnt[dst[e]], 1);
}

// ---------------------------------------------------------------------------
// Kernel 3: single-block exclusive scan over gCnt -> gOff, gCursor
// 1024 threads, each owns a contiguous chunk of bins.
// ---------------------------------------------------------------------------
__global__ void scan_kernel(int N, int E) {
    const int T   = 1024;
    const int tid = threadIdx.x;
    const int CH  = (N + T - 1) / T;
    const int base = tid * CH;

    int s = 0;
    for (int i = 0; i < CH; i++) {
        int idx = base + i;
        if (idx < N) s += gCnt[idx];
    }

    __shared__ int sh[1024];
    sh[tid] = s;
    __syncthreads();
    int total = s;
    for (int o = 1; o < T; o <<= 1) {
        int v = (tid >= o) ? sh[tid - o] : 0;
        __syncthreads();
        sh[tid] += v;
        __syncthreads();
    }
    int run = sh[tid] - total;   // exclusive prefix of this chunk

    for (int i = 0; i < CH; i++) {
        int idx = base + i;
        if (idx < N) {
            gOff[idx]    = run;
            gCursor[idx] = run;
            run += gCnt[idx];
        }
    }
    if (tid == T - 1) gOff[N] = E;
}

// ---------------------------------------------------------------------------
// Kernel 4: scatter edges into dst-sorted order
// ---------------------------------------------------------------------------
__global__ void scatter_kernel(const int* __restrict__ src,
                               const int* __restrict__ dst, int E) {
    int e = blockIdx.x * blockDim.x + threadIdx.x;
    if (e >= E) return;
    int d = dst[e];
    int pos = atomicAdd(&gCursor[d], 1);
    gSorted[pos] = make_int4(src[e], d, e, 0);
}

// ---------------------------------------------------------------------------
// Kernel 5: edge pass 1 over SORTED edges.
// 16 lanes/edge, 4 edges/warp (2 per 16-group, batched loads for MLP).
// B[dst] hits L1 because consecutive edges share dst.
// ---------------------------------------------------------------------------
__global__ void edge_pass1(const float* __restrict__ w2,
                           const float* __restrict__ b2, int E) {
    const int lane   = threadIdx.x & 31;
    const int sub    = lane & 15;
    const int grp    = lane >> 4;
    const int warp   = blockIdx.x * (blockDim.x >> 5) + (threadIdx.x >> 5);
    const int nwarps = gridDim.x * (blockDim.x >> 5);

    float w2v[8];
#pragma unroll
    for (int i = 0; i < 8; i++) w2v[i] = __ldg(&w2[sub * 8 + i]);
    const float b2v = __ldg(b2);

    const uint4* A4 = reinterpret_cast<const uint4*>(gA);
    const uint4* B4 = reinterpret_cast<const uint4*>(gB);

    for (int eb = warp * 4; eb < E; eb += nwarps * 4) {
        int   e[2];
        int   dd[2];
        uint4 av[2], bv[2];
        bool  valid[2];
#pragma unroll
        for (int j = 0; j < 2; j++) {
            e[j] = eb + grp * 2 + j;
            valid[j] = (e[j] < E);
            int4 ed = valid[j] ? gSorted[e[j]] : make_int4(0, 0, 0, 0);
            dd[j] = ed.y;
            av[j] = A4[ed.x * 16 + sub];
            bv[j] = B4[ed.y * 16 + sub];
        }
#pragma unroll
        for (int j = 0; j < 2; j++) {
            const __half2* ah = reinterpret_cast<const __half2*>(&av[j]);
            const __half2* bh = reinterpret_cast<const __half2*>(&bv[j]);
            float p = 0.0f;
#pragma unroll
            for (int i = 0; i < 4; i++) {
                float2 a2 = __half22float2(ah[i]);
                float2 c2 = __half22float2(bh[i]);
                p = fmaf(fmaxf(a2.x + c2.x, 0.0f), w2v[2 * i],     p);
                p = fmaf(fmaxf(a2.y + c2.y, 0.0f), w2v[2 * i + 1], p);
            }
#pragma unroll
            for (int o = 8; o > 0; o >>= 1)
                p += __shfl_xor_sync(0xFFFFFFFFu, p, o);

            if (sub == 0 && valid[j]) {
                float ev = expf(p + b2v);
                gEsort[e[j]] = ev;
                atomicAdd(&gDenom[dd[j]], ev);
            }
        }
    }
}

// ---------------------------------------------------------------------------
// Kernel 6: pass 2 — warp per node, NO atomics.
// alpha = e * (1/denom); scatter to original edge slot; yhat[d] = sum(y[src]*alpha)
// ---------------------------------------------------------------------------
__global__ void edge_pass2(const float* __restrict__ y,
                           float* __restrict__ alpha_out,
                           float* __restrict__ yhat, int N) {
    const int lane = threadIdx.x & 31;
    const int node = blockIdx.x * (blockDim.x >> 5) + (threadIdx.x >> 5);
    if (node >= N) return;

    const int start = gOff[node];
    const int end   = gOff[node + 1];
    const float inv = 1.0f / gDenom[node];   // inf if no edges: unused

    float sum = 0.0f;
    for (int i = start + lane; i < end; i += 32) {
        int4  ed = gSorted[i];
        float a  = gEsort[i] * inv;
        alpha_out[ed.z] = a;
        sum += __ldg(&y[ed.x]) * a;
    }
#pragma unroll
    for (int o = 16; o > 0; o >>= 1)
        sum += __shfl_xor_sync(0xFFFFFFFFu, sum, o);

    if (lane == 0) yhat[node] = sum;
}

// ---------------------------------------------------------------------------
extern "C" void kernel_launch(void* const* d_in, const int* in_sizes, int n_in,
                              void* d_out, int out_size) {
    const float* x  = (const float*)d_in[0];
    const float* y  = (const float*)d_in[1];
    const int*   ei = (const int*)  d_in[2];
    const float* w1 = (const float*)d_in[3];
    const float* b1 = (const float*)d_in[4];
    const float* w2 = (const float*)d_in[5];
    const float* b2 = (const float*)d_in[6];

    const int N = in_sizes[1];        // y has N elements
    const int E = in_sizes[2] / 2;    // edge_index is [2, E]

    float* yhat  = (float*)d_out;         // first N elements
    float* alpha = (float*)d_out + N;     // next E elements

    const int* src = ei;
    const int* dst = ei + E;

    init_kernel<<<(N + 255) / 256, 256>>>(N);
    precompute_ab<<<(N + TR - 1) / TR, 256>>>(x, w1, b1, N);
    hist_kernel<<<(E + 255) / 256, 256>>>(dst, E);
    scan_kernel<<<1, 1024>>>(N, E);
    scatter_kernel<<<(E + 255) / 256, 256>>>(src, dst, E);
    edge_pass1<<<1184, 256>>>(w2, b2, E);
    edge_pass2<<<(N * 32 + 255) / 256, 256>>>(y, alpha, yhat, N);
}

// round 6
// speedup vs baseline: 1.5185x; 1.5185x over previous
#include <cuda_runtime.h>
#include <cuda_fp16.h>

// Problem constants (fixed by the dataset)
#define NMAX 50048
#define EMAX 1600000
#define WDIM 64
#define HDIM 128

// Scratch (allocation-free rule: __device__ globals)
__device__ __half gA[NMAX * HDIM];     // x @ w1[0:64,:]  + b1
__device__ __half gB[NMAX * HDIM];     // x @ w1[64:128,:]
__device__ int    gCnt[NMAX];          // per-dst edge count
__device__ int    gOff[NMAX + 1];      // exclusive prefix (bin starts)
__device__ int    gCursor[NMAX];       // scatter cursors
__device__ int    gPart[256];          // per-block partial sums for scan
__device__ int2   gSortedE[EMAX];      // {src, orig_e} grouped by dst
__device__ float  gEsort[EMAX];        // exp(logit) in sorted order

// ---------------------------------------------------------------------------
// Kernel 0: zero histogram counters
// ---------------------------------------------------------------------------
__global__ void init_kernel(int N) {
    int i = blockIdx.x * blockDim.x + threadIdx.x;
    if (i < N) gCnt[i] = 0;
}

// ---------------------------------------------------------------------------
// Kernel 1: per-node precompute  A[n][j] = sum_k x[n][k]*w1[k][j] + b1[j]
//                                B[n][j] = sum_k x[n][k]*w1[64+k][j]
// ---------------------------------------------------------------------------
#define TR 16
__global__ void precompute_ab(const float* __restrict__ x,
                              const float* __restrict__ w1,
                              const float* __restrict__ b1, int N) {
    __shared__ float xs[TR][WDIM];
    const int row0 = blockIdx.x * TR;
    const int tid  = threadIdx.x;

    for (int i = tid; i < TR * WDIM; i += 256) {
        int r = i >> 6, k = i & 63;
        int gr = row0 + r;
        xs[r][k] = (gr < N) ? x[gr * WDIM + k] : 0.0f;
    }
    __syncthreads();

    const int col  = tid & 127;
    const int half = tid >> 7;   // 0 -> A, 1 -> B
    const float* wbase = w1 + half * WDIM * HDIM + col;

    float acc[TR];
#pragma unroll
    for (int r = 0; r < TR; r++) acc[r] = 0.0f;

#pragma unroll 8
    for (int k = 0; k < WDIM; k++) {
        float w = __ldg(wbase + k * HDIM);
#pragma unroll
        for (int r = 0; r < TR; r++) acc[r] += xs[r][k] * w;
    }

    const float bias = (half == 0) ? __ldg(&b1[col]) : 0.0f;
    __half* out = (half == 0) ? gA : gB;
#pragma unroll
    for (int r = 0; r < TR; r++) {
        int gr = row0 + r;
        if (gr < N) out[gr * HDIM + col] = __float2half_rn(acc[r] + bias);
    }
}

// ---------------------------------------------------------------------------
// Kernel 2: histogram of dst
// ---------------------------------------------------------------------------
__global__ void hist_kernel(const int* __restrict__ dst, int E) {
    int e = blockIdx.x * blockDim.x + threadIdx.x;
    if (e < E) atomicAdd(&gCnt[dst[e]], 1);
}

// ---------------------------------------------------------------------------
// Scan (3 fast kernels replacing the 78.9us single-block scan)
// ---------------------------------------------------------------------------
// 3a: per-block sums (256 bins per block)
__global__ void scan_partials(int N) {
    __shared__ int sh[256];
    int idx = blockIdx.x * 256 + threadIdx.x;
    int v = (idx < N) ? gCnt[idx] : 0;
    sh[threadIdx.x] = v;
    __syncthreads();
    for (int o = 128; o > 0; o >>= 1) {
        if (threadIdx.x < o) sh[threadIdx.x] += sh[threadIdx.x + o];
        __syncthreads();
    }
    if (threadIdx.x == 0) gPart[blockIdx.x] = sh[0];
}

// 3b: exclusive scan of the (<=256) partials, single block
__global__ void scan_tops(int nblocks) {
    __shared__ int sh[256];
    int tid = threadIdx.x;
    int v = (tid < nblocks) ? gPart[tid] : 0;
    sh[tid] = v;
    __syncthreads();
    for (int o = 1; o < 256; o <<= 1) {
        int t = (tid >= o) ? sh[tid - o] : 0;
        __syncthreads();
        sh[tid] += t;
        __syncthreads();
    }
    if (tid < nblocks) gPart[tid] = sh[tid] - v;   // exclusive
}

// 3c: intra-block exclusive scan + partial offset -> gOff, gCursor
__global__ void scan_final(int N, int E) {
    __shared__ int sh[256];
    int tid = threadIdx.x;
    int idx = blockIdx.x * 256 + tid;
    int v = (idx < N) ? gCnt[idx] : 0;
    sh[tid] = v;
    __syncthreads();
    for (int o = 1; o < 256; o <<= 1) {
        int t = (tid >= o) ? sh[tid - o] : 0;
        __syncthreads();
        sh[tid] += t;
        __syncthreads();
    }
    int excl = sh[tid] - v + gPart[blockIdx.x];
    if (idx < N) {
        gOff[idx]    = excl;
        gCursor[idx] = excl;
        if (idx == N - 1) gOff[N] = excl + v;   // == E
    }
}

// ---------------------------------------------------------------------------
// Kernel 4: scatter edges into dst-grouped order (8B records)
// ---------------------------------------------------------------------------
__global__ void scatter_kernel(const int* __restrict__ src,
                               const int* __restrict__ dst, int E) {
    int e = blockIdx.x * blockDim.x + threadIdx.x;
    if (e >= E) return;
    int d = dst[e];
    int pos = atomicAdd(&gCursor[d], 1);
    gSortedE[pos] = make_int2(src[e], e);
}

// ---------------------------------------------------------------------------
// Kernel 5: FUSED per-node kernel — warp per node, no atomics.
// Loads B[node] once into registers. For each incident edge: gather A[src],
// logit = w2.relu(A+B)+b2, ev=exp(logit). denom accumulated in registers.
// Then alpha = ev/denom scattered to original slot, yhat[node] = sum(y*alpha).
// ---------------------------------------------------------------------------
__global__ void __launch_bounds__(256) fused_node(
        const float* __restrict__ y,
        const float* __restrict__ w2,
        const float* __restrict__ b2,
        float* __restrict__ alpha_out,
        float* __restrict__ yhat, int N) {
    const int lane = threadIdx.x & 31;
    const int node = blockIdx.x * (blockDim.x >> 5) + (threadIdx.x >> 5);
    if (node >= N) return;

    const int start = gOff[node];
    const int end   = gOff[node + 1];

    // B[node]: 128 halves = 32 uint2; lane holds halves [4*lane .. 4*lane+3]
    const uint2* A2u = reinterpret_cast<const uint2*>(gA);
    const uint2* B2u = reinterpret_cast<const uint2*>(gB);
    const uint2  braw = B2u[node * 32 + lane];
    const __half2 bh0 = *reinterpret_cast<const __half2*>(&braw.x);
    const __half2 bh1 = *reinterpret_cast<const __half2*>(&braw.y);

    const float4 w2v = reinterpret_cast<const float4*>(w2)[lane];
    const float  b2v = __ldg(b2);
    const __half2 z2 = __float2half2_rn(0.0f);

    float denom = 0.0f;

    for (int base = start; base < end; base += 32) {
        const int n = min(32, end - base);
        int2 rec = (base + lane < end) ? gSortedE[base + lane]
                                       : make_int2(0, 0);
        float my_ev = 0.0f;

        int j = 0;
        for (; j + 1 < n; j += 2) {
            int s0 = __shfl_sync(0xFFFFFFFFu, rec.x, j);
            int s1 = __shfl_sync(0xFFFFFFFFu, rec.x, j + 1);
            uint2 ar0 = A2u[s0 * 32 + lane];
            uint2 ar1 = A2u[s1 * 32 + lane];

            __half2 h00 = __hmax2(__hadd2(*reinterpret_cast<__half2*>(&ar0.x), bh0), z2);
            __half2 h01 = __hmax2(__hadd2(*reinterpret_cast<__half2*>(&ar0.y), bh1), z2);
            __half2 h10 = __hmax2(__hadd2(*reinterpret_cast<__half2*>(&ar1.x), bh0), z2);
            __half2 h11 = __hmax2(__hadd2(*reinterpret_cast<__half2*>(&ar1.y), bh1), z2);

            float2 f00 = __half22float2(h00), f01 = __half22float2(h01);
            float2 f10 = __half22float2(h10), f11 = __half22float2(h11);
            float p0 = fmaf(f00.x, w2v.x, fmaf(f00.y, w2v.y,
                       fmaf(f01.x, w2v.z, f01.y * w2v.w)));
            float p1 = fmaf(f10.x, w2v.x, fmaf(f10.y, w2v.y,
                       fmaf(f11.x, w2v.z, f11.y * w2v.w)));
#pragma unroll
            for (int o = 16; o > 0; o >>= 1) {
                p0 += __shfl_xor_sync(0xFFFFFFFFu, p0, o);
                p1 += __shfl_xor_sync(0xFFFFFFFFu, p1, o);
            }
            if (lane == j)     my_ev = expf(p0 + b2v);
            if (lane == j + 1) my_ev = expf(p1 + b2v);
        }
        if (j < n) {
            int s0 = __shfl_sync(0xFFFFFFFFu, rec.x, j);
            uint2 ar0 = A2u[s0 * 32 + lane];
            __half2 h00 = __hmax2(__hadd2(*reinterpret_cast<__half2*>(&ar0.x), bh0), z2);
            __half2 h01 = __hmax2(__hadd2(*reinterpret_cast<__half2*>(&ar0.y), bh1), z2);
            float2 f00 = __half22float2(h00), f01 = __half22float2(h01);
            float p0 = fmaf(f00.x, w2v.x, fmaf(f00.y, w2v.y,
                       fmaf(f01.x, w2v.z, f01.y * w2v.w)));
#pragma unroll
            for (int o = 16; o > 0; o >>= 1)
                p0 += __shfl_xor_sync(0xFFFFFFFFu, p0, o);
            if (lane == j) my_ev = expf(p0 + b2v);
        }

        if (base + lane < end) gEsort[base + lane] = my_ev;
        float t = my_ev;
#pragma unroll
        for (int o = 16; o > 0; o >>= 1)
            t += __shfl_xor_sync(0xFFFFFFFFu, t, o);
        denom += t;
    }

    const float inv = 1.0f / denom;   // node with no edges: loop below empty

    float sum = 0.0f;
    for (int i = start + lane; i < end; i += 32) {
        int2  rec = gSortedE[i];
        float a   = gEsort[i] * inv;
        alpha_out[rec.y] = a;
        sum += __ldg(&y[rec.x]) * a;
    }
#pragma unroll
    for (int o = 16; o > 0; o >>= 1)
        sum += __shfl_xor_sync(0xFFFFFFFFu, sum, o);
    if (lane == 0) yhat[node] = sum;
}

// ---------------------------------------------------------------------------
extern "C" void kernel_launch(void* const* d_in, const int* in_sizes, int n_in,
                              void* d_out, int out_size) {
    const float* x  = (const float*)d_in[0];
    const float* y  = (const float*)d_in[1];
    const int*   ei = (const int*)  d_in[2];
    const float* w1 = (const float*)d_in[3];
    const float* b1 = (const float*)d_in[4];
    const float* w2 = (const float*)d_in[5];
    const float* b2 = (const float*)d_in[6];

    const int N = in_sizes[1];        // y has N elements
    const int E = in_sizes[2] / 2;    // edge_index is [2, E]

    float* yhat  = (float*)d_out;         // first N elements
    float* alpha = (float*)d_out + N;     // next E elements

    const int* src = ei;
    const int* dst = ei + E;

    const int scanBlocks = (N + 255) / 256;   // 196 <= 256

    init_kernel<<<(N + 255) / 256, 256>>>(N);
    precompute_ab<<<(N + TR - 1) / TR, 256>>>(x, w1, b1, N);
    hist_kernel<<<(E + 255) / 256, 256>>>(dst, E);
    scan_partials<<<scanBlocks, 256>>>(N);
    scan_tops<<<1, 256>>>(scanBlocks);
    scan_final<<<scanBlocks, 256>>>(N, E);
    scatter_kernel<<<(E + 255) / 256, 256>>>(src, dst, E);
    fused_node<<<(N + 7) / 8, 256>>>(y, w2, b2, alpha, yhat, N);
}

// round 8
// speedup vs baseline: 1.6215x; 1.0678x over previous
#include <cuda_runtime.h>
#include <cuda_fp16.h>

// Problem constants (fixed by the dataset)
#define NMAX 50048
#define EMAX 1600000
#define WDIM 64
#define HDIM 128

// Scratch (allocation-free rule: __device__ globals)
__device__ __half gA[NMAX * HDIM];     // x @ w1[0:64,:]  + b1
__device__ __half gB[NMAX * HDIM];     // x @ w1[64:128,:]
__device__ int    gCnt[NMAX];          // per-dst edge count
__device__ int    gOff[NMAX + 1];      // exclusive prefix (bin starts)
__device__ int    gCursor[NMAX];       // scatter cursors
__device__ int    gPart[256];          // per-block partial sums for scan
__device__ int2   gSortedE[EMAX];      // {src, orig_e} grouped by dst
__device__ float  gEsort[EMAX];        // exp(logit) in sorted order

// ---------------------------------------------------------------------------
// Kernel 0: zero histogram counters
// ---------------------------------------------------------------------------
__global__ void init_kernel(int N) {
    int i = blockIdx.x * blockDim.x + threadIdx.x;
    if (i < N) gCnt[i] = 0;
}

// ---------------------------------------------------------------------------
// Kernel 1: per-node precompute  A[n][j] = sum_k x[n][k]*w1[k][j] + b1[j]
//                                B[n][j] = sum_k x[n][k]*w1[64+k][j]
// ---------------------------------------------------------------------------
#define TR 16
__global__ void precompute_ab(const float* __restrict__ x,
                              const float* __restrict__ w1,
                              const float* __restrict__ b1, int N) {
    __shared__ float xs[TR][WDIM];
    const int row0 = blockIdx.x * TR;
    const int tid  = threadIdx.x;

    for (int i = tid; i < TR * WDIM; i += 256) {
        int r = i >> 6, k = i & 63;
        int gr = row0 + r;
        xs[r][k] = (gr < N) ? x[gr * WDIM + k] : 0.0f;
    }
    __syncthreads();

    const int col  = tid & 127;
    const int half = tid >> 7;   // 0 -> A, 1 -> B
    const float* wbase = w1 + half * WDIM * HDIM + col;

    float acc[TR];
#pragma unroll
    for (int r = 0; r < TR; r++) acc[r] = 0.0f;

#pragma unroll 8
    for (int k = 0; k < WDIM; k++) {
        float w = __ldg(wbase + k * HDIM);
#pragma unroll
        for (int r = 0; r < TR; r++) acc[r] += xs[r][k] * w;
    }

    const float bias = (half == 0) ? __ldg(&b1[col]) : 0.0f;
    __half* out = (half == 0) ? gA : gB;
#pragma unroll
    for (int r = 0; r < TR; r++) {
        int gr = row0 + r;
        if (gr < N) out[gr * HDIM + col] = __float2half_rn(acc[r] + bias);
    }
}

// ---------------------------------------------------------------------------
// Kernel 2: histogram of dst
// ---------------------------------------------------------------------------
__global__ void hist_kernel(const int* __restrict__ dst, int E) {
    int e = blockIdx.x * blockDim.x + threadIdx.x;
    if (e < E) atomicAdd(&gCnt[dst[e]], 1);
}

// ---------------------------------------------------------------------------
// Scan: 3 small kernels
// ---------------------------------------------------------------------------
__global__ void scan_partials(int N) {
    __shared__ int sh[256];
    int idx = blockIdx.x * 256 + threadIdx.x;
    int v = (idx < N) ? gCnt[idx] : 0;
    sh[threadIdx.x] = v;
    __syncthreads();
    for (int o = 128; o > 0; o >>= 1) {
        if (threadIdx.x < o) sh[threadIdx.x] += sh[threadIdx.x + o];
        __syncthreads();
    }
    if (threadIdx.x == 0) gPart[blockIdx.x] = sh[0];
}

__global__ void scan_tops(int nblocks) {
    __shared__ int sh[256];
    int tid = threadIdx.x;
    int v = (tid < nblocks) ? gPart[tid] : 0;
    sh[tid] = v;
    __syncthreads();
    for (int o = 1; o < 256; o <<= 1) {
        int t = (tid >= o) ? sh[tid - o] : 0;
        __syncthreads();
        sh[tid] += t;
        __syncthreads();
    }
    if (tid < nblocks) gPart[tid] = sh[tid] - v;   // exclusive
}

__global__ void scan_final(int N, int E) {
    __shared__ int sh[256];
    int tid = threadIdx.x;
    int idx = blockIdx.x * 256 + tid;
    int v = (idx < N) ? gCnt[idx] : 0;
    sh[tid] = v;
    __syncthreads();
    for (int o = 1; o < 256; o <<= 1) {
        int t = (tid >= o) ? sh[tid - o] : 0;
        __syncthreads();
        sh[tid] += t;
        __syncthreads();
    }
    int excl = sh[tid] - v + gPart[blockIdx.x];
    if (idx < N) {
        gOff[idx]    = excl;
        gCursor[idx] = excl;
        if (idx == N - 1) gOff[N] = excl + v;   // == E
    }
}

// ---------------------------------------------------------------------------
// Kernel 4: scatter edges into dst-grouped order (8B records)
// ---------------------------------------------------------------------------
__global__ void scatter_kernel(const int* __restrict__ src,
                               const int* __restrict__ dst, int E) {
    int e = blockIdx.x * blockDim.x + threadIdx.x;
    if (e >= E) return;
    int d = dst[e];
    int pos = atomicAdd(&gCursor[d], 1);
    gSortedE[pos] = make_int2(src[e], e);
}

// ---------------------------------------------------------------------------
// Kernel 5: FUSED per-node kernel — warp per node, no atomics.
// 8 lanes per edge (16 hidden dims each, 2x LDG.128), 4 subgroups x 2 edges
// in flight per iteration = 8 independent edges hiding latency.
// Reduction per edge: 3 xor-shfls within the 8-lane subgroup.
// ---------------------------------------------------------------------------
__global__ void __launch_bounds__(256) fused_node(
        const float* __restrict__ y,
        const float* __restrict__ w2,
        const float* __restrict__ b2,
        float* __restrict__ alpha_out,
        float* __restrict__ yhat, int N) {
    const int lane = threadIdx.x & 31;
    const int sub  = lane & 7;          // lane within 8-group
    const int g    = lane >> 3;         // subgroup 0..3
    const int node = blockIdx.x * (blockDim.x >> 5) + (threadIdx.x >> 5);
    if (node >= N) return;

    const int start = gOff[node];
    const int end   = gOff[node + 1];

    const uint4* A4 = reinterpret_cast<const uint4*>(gA);  // 16 uint4 / row
    const uint4* B4 = reinterpret_cast<const uint4*>(gB);

    // B[node] halves [16*sub, 16*sub+16): 2 x uint4 = 8 half2
    uint4 br0 = B4[node * 16 + sub * 2];
    uint4 br1 = B4[node * 16 + sub * 2 + 1];
    __half2 bh[8];
    {
        const __half2* p0 = reinterpret_cast<const __half2*>(&br0);
        const __half2* p1 = reinterpret_cast<const __half2*>(&br1);
#pragma unroll
        for (int i = 0; i < 4; i++) { bh[i] = p0[i]; bh[4 + i] = p1[i]; }
    }

    // w2 coefficients [16*sub, 16*sub+16)
    float w2v[16];
#pragma unroll
    for (int i = 0; i < 4; i++) {
        float4 t = reinterpret_cast<const float4*>(w2)[sub * 4 + i];
        w2v[4 * i] = t.x; w2v[4 * i + 1] = t.y;
        w2v[4 * i + 2] = t.z; w2v[4 * i + 3] = t.w;
    }
    const float  b2v = __ldg(b2);
    const __half2 z2 = __float2half2_rn(0.0f);

    float denom_part = 0.0f;

    for (int base = start; base < end; base += 8) {
        // two edges for this subgroup: base+g and base+g+4
        int  e0 = base + g, e1 = base + g + 4;
        bool v0 = e0 < end, v1 = e1 < end;
        int  s0 = v0 ? gSortedE[e0].x : 0;   // broadcast load (same addr in subgroup)
        int  s1 = v1 ? gSortedE[e1].x : 0;

        uint4 a00 = A4[s0 * 16 + sub * 2];
        uint4 a01 = A4[s0 * 16 + sub * 2 + 1];
        uint4 a10 = A4[s1 * 16 + sub * 2];
        uint4 a11 = A4[s1 * 16 + sub * 2 + 1];

        float p0 = 0.0f, p1 = 0.0f;
        {
            const __half2* q0 = reinterpret_cast<const __half2*>(&a00);
            const __half2* q1 = reinterpret_cast<const __half2*>(&a01);
            const __half2* r0 = reinterpret_cast<const __half2*>(&a10);
            const __half2* r1 = reinterpret_cast<const __half2*>(&a11);
#pragma unroll
            for (int i = 0; i < 4; i++) {
                float2 f;
                f = __half22float2(__hmax2(__hadd2(q0[i], bh[i]), z2));
                p0 = fmaf(f.x, w2v[2 * i],     fmaf(f.y, w2v[2 * i + 1], p0));
                f = __half22float2(__hmax2(__hadd2(q1[i], bh[4 + i]), z2));
                p0 = fmaf(f.x, w2v[8 + 2 * i], fmaf(f.y, w2v[9 + 2 * i], p0));
                f = __half22float2(__hmax2(__hadd2(r0[i], bh[i]), z2));
                p1 = fmaf(f.x, w2v[2 * i],     fmaf(f.y, w2v[2 * i + 1], p1));
                f = __half22float2(__hmax2(__hadd2(r1[i], bh[4 + i]), z2));
                p1 = fmaf(f.x, w2v[8 + 2 * i], fmaf(f.y, w2v[9 + 2 * i], p1));
            }
        }
        // reduce within 8-lane subgroup: 3 shfls each, two chains interleaved
#pragma unroll
        for (int o = 4; o > 0; o >>= 1) {
            p0 += __shfl_xor_sync(0xFFFFFFFFu, p0, o);
            p1 += __shfl_xor_sync(0xFFFFFFFFu, p1, o);
        }
        if (sub == 0) {
            if (v0) { float ev = __expf(p0 + b2v); gEsort[e0] = ev; denom_part += ev; }
            if (v1) { float ev = __expf(p1 + b2v); gEsort[e1] = ev; denom_part += ev; }
        }
    }

    // total denom over the warp
#pragma unroll
    for (int o = 16; o > 0; o >>= 1)
        denom_part += __shfl_xor_sync(0xFFFFFFFFu, denom_part, o);
    const float inv = 1.0f / denom_part;

    // pass 2: alpha + weighted sum, coalesced over the node's segment
    float sum = 0.0f;
    for (int i = start + lane; i < end; i += 32) {
        int2  rec = gSortedE[i];
        float a   = gEsort[i] * inv;
        alpha_out[rec.y] = a;
        sum += __ldg(&y[rec.x]) * a;
    }
#pragma unroll
    for (int o = 16; o > 0; o >>= 1)
        sum += __shfl_xor_sync(0xFFFFFFFFu, sum, o);
    if (lane == 0) yhat[node] = sum;
}

// ---------------------------------------------------------------------------
extern "C" void kernel_launch(void* const* d_in, const int* in_sizes, int n_in,
                              void* d_out, int out_size) {
    const float* x  = (const float*)d_in[0];
    const float* y  = (const float*)d_in[1];
    const int*   ei = (const int*)  d_in[2];
    const float* w1 = (const float*)d_in[3];
    const float* b1 = (const float*)d_in[4];
    const float* w2 = (const float*)d_in[5];
    const float* b2 = (const float*)d_in[6];

    const int N = in_sizes[1];        // y has N elements
    const int E = in_sizes[2] / 2;    // edge_index is [2, E]

    float* yhat  = (float*)d_out;         // first N elements
    float* alpha = (float*)d_out + N;     // next E elements

    const int* src = ei;
    const int* dst = ei + E;

    const int scanBlocks = (N + 255) / 256;   // 196 <= 256

    init_kernel<<<(N + 255) / 256, 256>>>(N);
    precompute_ab<<<(N + TR - 1) / TR, 256>>>(x, w1, b1, N);
    hist_kernel<<<(E + 255) / 256, 256>>>(dst, E);
    scan_partials<<<scanBlocks, 256>>>(N);
    scan_tops<<<1, 256>>>(scanBlocks);
    scan_final<<<scanBlocks, 256>>>(N, E);
    scatter_kernel<<<(E + 255) / 256, 256>>>(src, dst, E);
    fused_node<<<(N + 7) / 8, 256>>>(y, w2, b2, alpha, yhat, N);
}